// round 14
// baseline (speedup 1.0000x reference)
#include <cuda_runtime.h>
#include <cuda_bf16.h>
#include <stdint.h>
#include <math.h>

#define N_ENTC 20000
#define NRELC  460
#define HC     128
#define NEC    400000
#define NBC    1024
#define NTC    8
#define H3C    384
#define SLOPE  0.22916666666666666f
#define KPRE   384
#define KPAD   480
#define MT_STR 512

// ---------------- fp32 scratch ----------------
constexpr size_t O_MREL  = 0;
constexpr size_t O_MRELT = O_MREL + (size_t)NRELC * HC;
constexpr size_t O_QREL  = O_MRELT + (size_t)HC * MT_STR;
constexpr size_t O_AMAT  = O_QREL + (size_t)NBC * HC;
constexpr size_t O_GIALL = O_AMAT + (size_t)NBC * NRELC;
constexpr size_t O_WHHT  = O_GIALL + (size_t)(NTC + 1) * NBC * H3C;
constexpr size_t O_WH1T  = O_WHHT + 49152;
constexpr size_t O_WH2T  = O_WH1T + 16384;
constexpr size_t O_WATT  = O_WH2T + 16384;
constexpr size_t O_WALT  = O_WATT + 16384;
constexpr size_t O_WM1T  = O_WALT + 16384;
constexpr size_t O_WM2T  = O_WM1T + 32768;
constexpr size_t O_ACC_  = O_WM2T + 32768;
constexpr size_t O_ACC   = (O_ACC_ + 1) & ~(size_t)1;
constexpr size_t O_INT   = O_ACC + 8;
constexpr size_t N_INTS  = (size_t)N_ENTC + (N_ENTC + 1) + N_ENTC + NEC + 64;
constexpr size_t TOTALF  = O_INT + N_INTS;
__device__ __align__(16) float d_buf[TOTALF];

// ---------------- bf16 scratch ----------------
__device__ __align__(16) __nv_bfloat16 g_aggb[(size_t)N_ENTC * HC];
__device__ __align__(16) __nv_bfloat16 g_B3[HC * KPRE];
__device__ __align__(16) __nv_bfloat16 g_entb[(size_t)N_ENTC * HC];
__device__ __align__(16) __nv_bfloat16 g_relb[NRELC * HC];
__device__ __align__(16) __nv_bfloat16 g_prebf[(size_t)N_ENTC * HC];
__device__ __align__(16) __nv_bfloat16 g_alnbf[(size_t)N_ENTC * HC];
__device__ __align__(16) __nv_bfloat16 g_walb[HC * HC];
__device__ __align__(16) __nv_bfloat16 g_wihb[H3C * HC];
__device__ __align__(16) __nv_bfloat16 g_mrelTb[HC * KPAD];
__device__ __align__(16) __nv_bfloat16 g_Xb[(size_t)(NTC + 1) * NBC * HC];
__device__ __align__(16) __nv_bfloat16 g_attnb[(size_t)NTC * NBC * KPAD];
__device__ __align__(16) __nv_bfloat16 g_svecb[(size_t)NBC * HC];

// ---------------- reductions ----------------
__device__ __forceinline__ float blockReduceSum(float v) {
    __shared__ float sh[32];
    int tid = threadIdx.x;
    __syncthreads();
    #pragma unroll
    for (int o = 16; o > 0; o >>= 1) v += __shfl_xor_sync(0xffffffffu, v, o);
    if ((tid & 31) == 0) sh[tid >> 5] = v;
    __syncthreads();
    float r = 0.f;
    if (tid < 32) {
        int nw = (blockDim.x + 31) >> 5;
        r = (tid < nw) ? sh[tid] : 0.f;
        #pragma unroll
        for (int o = 16; o > 0; o >>= 1) r += __shfl_xor_sync(0xffffffffu, r, o);
    }
    return r;
}

__device__ __forceinline__ void sig_sp(float x, float& sig, float& sp) {
    float ax = fabsf(x);
    if (ax < 0.5f) {
        float x2 = x * x;
        sig = 0.5f + x * (0.25f + x2 * (-0.0208333333f + x2 * 0.0020833333f));
        sp  = 0.69314718f + 0.5f * x
            + x2 * (0.125f + x2 * (-0.0052083333f + x2 * 0.00034722222f));
    } else {
        float e = __expf(-ax);
        sig = (x >= 0.f) ? 1.f / (1.f + e) : e / (1.f + e);
        sp  = fmaxf(x, 0.f) + __logf(1.f + e);
    }
}
__device__ __forceinline__ float sigm(float x) { return 1.f / (1.f + __expf(-x)); }

// ---------------- init ----------------
__global__ void k_init(const float* __restrict__ Wn, const float* __restrict__ Wl,
                       const float* __restrict__ Wev, const float* __restrict__ wih,
                       const float* __restrict__ whh, const float* __restrict__ Wal,
                       const float* __restrict__ Wh1, const float* __restrict__ Wh2,
                       const float* __restrict__ Wat, const float* __restrict__ Wm1,
                       const float* __restrict__ Wm2, const float* __restrict__ rel,
                       int* deg, int* cursor, double* acc, int* done, float* F) {
    int i = blockIdx.x * blockDim.x + threadIdx.x;  // grid 640*256
    if (i < N_ENTC) { deg[i] = 0; cursor[i] = 0; }
    if (i == 0) { acc[0] = 0.0; acc[1] = 0.0; acc[2] = 0.0; done[0] = 0; }
    if (i < HC * KPRE) {
        int n = i / KPRE, k = i % KPRE;
        float v = (k < 128) ? Wn[k * 128 + n]
                : (k < 256) ? Wl[(k - 128) * 128 + n]
                            : Wev[(k - 256) * 128 + n];
        g_B3[i] = __float2bfloat16(v);
    }
    if (i < H3C * HC) g_wihb[i] = __float2bfloat16(wih[i]);
    if (i < HC * HC)  g_walb[i] = __float2bfloat16(Wal[i]);
    if (i < NRELC * HC) g_relb[i] = __float2bfloat16(rel[i]);
    if (i < HC * H3C) {
        int k = i / H3C, j = i % H3C;
        F[O_WHHT + i] = whh[j * 128 + k];
    }
    if (i < HC * HC) {
        int k = i / HC, j = i % HC;
        F[O_WH1T + i] = Wh1[j * HC + k];
        F[O_WH2T + i] = Wh2[j * HC + k];
        F[O_WATT + i] = Wat[j * HC + k];
        F[O_WALT + i] = Wal[j * HC + k];
    }
    if (i < 128 * 256) {
        int k = i / 256, j2 = i % 256;
        F[O_WM1T + i] = Wm1[j2 * 128 + k];
    }
    if (i < 256 * 128) {
        int k2 = i / 128, j = i % 128;
        F[O_WM2T + i] = Wm2[j * 256 + k2];
    }
    if (i < HC * (KPAD - NRELC)) {
        int j = i / (KPAD - NRELC), c = NRELC + i % (KPAD - NRELC);
        g_mrelTb[j * KPAD + c] = __float2bfloat16(0.f);
    }
    if (i < HC * (MT_STR - NRELC)) {
        int j = i / (MT_STR - NRELC), c = NRELC + i % (MT_STR - NRELC);
        F[O_MRELT + j * MT_STR + c] = 0.f;
    }
    if (i < NTC * NBC * (KPAD - NRELC)) {
        int row = i / (KPAD - NRELC), c = NRELC + i % (KPAD - NRELC);
        g_attnb[(size_t)row * KPAD + c] = __float2bfloat16(0.f);
    }
}

__global__ void k_count_entcvt(const int* __restrict__ dst, int* deg,
                               const float* __restrict__ ent) {
    int i = blockIdx.x * blockDim.x + threadIdx.x;
    if (i < NEC) atomicAdd(&deg[dst[i]], 1);
    if (i < N_ENTC * HC) g_entb[i] = __float2bfloat16(ent[i]);
}

__global__ void k_scanA(const int* __restrict__ deg, int* rowptr, int* bsums) {
    __shared__ int wsum[32];
    int tid = threadIdx.x, lane = tid & 31, wid = tid >> 5;
    int i = blockIdx.x * 1024 + tid;
    int v = (i < N_ENTC) ? deg[i] : 0;
    int x = v;
    #pragma unroll
    for (int o = 1; o < 32; o <<= 1) {
        int t = __shfl_up_sync(0xffffffffu, x, o);
        if (lane >= o) x += t;
    }
    if (lane == 31) wsum[wid] = x;
    __syncthreads();
    if (wid == 0) {
        int s = wsum[lane];
        #pragma unroll
        for (int o = 1; o < 32; o <<= 1) {
            int t = __shfl_up_sync(0xffffffffu, s, o);
            if (lane >= o) s += t;
        }
        wsum[lane] = s;
    }
    __syncthreads();
    int woff = (wid > 0) ? wsum[wid - 1] : 0;
    int incl = x + woff;
    if (i < N_ENTC) rowptr[i] = incl - v;
    if (tid == 1023) bsums[blockIdx.x] = incl;
}

__global__ void k_scanB(int* rowptr, const int* __restrict__ bsums, int nblk) {
    __shared__ int offs[32];
    __shared__ int total_s;
    int tid = threadIdx.x;
    if (tid < 32) {
        int v = (tid < nblk) ? bsums[tid] : 0;
        int x = v;
        #pragma unroll
        for (int o = 1; o < 32; o <<= 1) {
            int t = __shfl_up_sync(0xffffffffu, x, o);
            if (tid >= o) x += t;
        }
        offs[tid] = x - v;
        if (tid == 31) total_s = x;
    }
    __syncthreads();
    for (int i = tid; i < N_ENTC; i += blockDim.x)
        rowptr[i] += offs[i >> 10];
    if (tid == 0) rowptr[N_ENTC] = total_s;
}

__global__ void k_fill(const int* __restrict__ dst, const int* __restrict__ src,
                       const int* __restrict__ typ, const int* __restrict__ rowptr,
                       int* cursor, int* csr) {
    int e = blockIdx.x * blockDim.x + threadIdx.x;
    if (e < NEC) {
        int d = dst[e];
        int p = atomicAdd(&cursor[d], 1);
        csr[rowptr[d] + p] = src[e] | (typ[e] << 16);
    }
}

__global__ void k_aggregate(const int* __restrict__ rowptr, const int* __restrict__ csr) {
    int node = blockIdx.x;
    int c = threadIdx.x;  // 64
    __shared__ int s_src[256];
    __shared__ int s_typ[256];
    const __nv_bfloat162* entb = (const __nv_bfloat162*)g_entb;
    const __nv_bfloat162* relb = (const __nv_bfloat162*)g_relb;
    int beg = rowptr[node], end = rowptr[node + 1];
    int deg = end - beg;
    float ax = 0.f, ay = 0.f;
    for (int base = beg; base < end; base += 256) {
        int cnt = min(256, end - base);
        for (int i = c; i < cnt; i += 64) {
            int p = csr[base + i];
            s_src[i] = (p & 0xFFFF) << 6;
            s_typ[i] = ((unsigned)p >> 16) << 6;
        }
        __syncthreads();
        #pragma unroll 8
        for (int i = 0; i < cnt; i++) {
            __nv_bfloat162 ev = entb[s_src[i] + c];
            __nv_bfloat162 rv = relb[s_typ[i] + c];
            ax += __bfloat162float(ev.x) + __bfloat162float(rv.x);
            ay += __bfloat162float(ev.y) + __bfloat162float(rv.y);
        }
        __syncthreads();
    }
    float inv = (deg > 0) ? 1.f / (float)deg : 0.f;
    __nv_bfloat162 o;
    o.x = __float2bfloat16(ax * inv);
    o.y = __float2bfloat16(ay * inv);
    *(__nv_bfloat162*)(g_aggb + (size_t)node * HC + 2 * c) = o;
}

// ---------------- GEMM fragment helpers ----------------
#define BGM 128
#define BGN 128
#define BGK 32
#define SSTR 40
#define XSTR 136

#define MMA_STEP(As_, Bs_, STRA, kbaseA, kk, cacc)                                   \
    {                                                                                 \
        uint32_t a[2][4], b[8][2];                                                    \
        _Pragma("unroll")                                                             \
        for (int mt = 0; mt < 2; mt++) {                                              \
            int row = wm * 32 + mt * 16 + (lane & 15);                                \
            int col = (kbaseA) + (kk) + ((lane >> 4) << 3);                           \
            uint32_t addr = (uint32_t)__cvta_generic_to_shared((As_) + row * (STRA) + col); \
            asm volatile("ldmatrix.sync.aligned.m8n8.x4.shared.b16 {%0,%1,%2,%3},[%4];" \
                         : "=r"(a[mt][0]), "=r"(a[mt][1]), "=r"(a[mt][2]), "=r"(a[mt][3]) \
                         : "r"(addr));                                                \
        }                                                                             \
        _Pragma("unroll")                                                             \
        for (int np = 0; np < 4; np++) {                                              \
            int nrow = wn * 64 + np * 16 + ((lane >> 4) << 3) + (lane & 7);           \
            int ncol = (kk) + (((lane >> 3) & 1) << 3);                               \
            uint32_t addr = (uint32_t)__cvta_generic_to_shared((Bs_) + nrow * SSTR + ncol); \
            asm volatile("ldmatrix.sync.aligned.m8n8.x4.shared.b16 {%0,%1,%2,%3},[%4];" \
                         : "=r"(b[2 * np][0]), "=r"(b[2 * np][1]),                    \
                           "=r"(b[2 * np + 1][0]), "=r"(b[2 * np + 1][1])             \
                         : "r"(addr));                                                \
        }                                                                             \
        _Pragma("unroll")                                                             \
        for (int mt = 0; mt < 2; mt++)                                                \
            _Pragma("unroll")                                                         \
            for (int nt = 0; nt < 8; nt++)                                            \
                asm volatile(                                                         \
                    "mma.sync.aligned.m16n8k16.row.col.f32.bf16.bf16.f32 "            \
                    "{%0,%1,%2,%3},{%4,%5,%6,%7},{%8,%9},{%0,%1,%2,%3};"              \
                    : "+f"(cacc[mt][nt][0]), "+f"(cacc[mt][nt][1]),                   \
                      "+f"(cacc[mt][nt][2]), "+f"(cacc[mt][nt][3])                    \
                    : "r"(a[mt][0]), "r"(a[mt][1]), "r"(a[mt][2]), "r"(a[mt][3]),     \
                      "r"(b[nt][0]), "r"(b[nt][1]));                                  \
    }

// ---------------- score GEMM + fused final (pipelined, 2 blocks/SM) ----------------
__global__ __launch_bounds__(256, 2)
void k_score(const __nv_bfloat16* __restrict__ A, const __nv_bfloat16* __restrict__ B,
             float* __restrict__ Cf, const int* __restrict__ trip, double* acc,
             int* done, int nblocks, int write_final, int M, int N) {
    __shared__ __nv_bfloat16 As[BGM * SSTR];
    __shared__ __nv_bfloat16 Bs[BGN * SSTR];
    int tid = threadIdx.x;
    int lane = tid & 31, wid = tid >> 5;
    int wm = wid & 3, wn = wid >> 2;
    int rowBase = blockIdx.y * BGM;
    int colBase = blockIdx.x * BGN;
    float c[2][8][4];
    #pragma unroll
    for (int i = 0; i < 2; i++)
        #pragma unroll
        for (int j = 0; j < 8; j++)
            #pragma unroll
            for (int q = 0; q < 4; q++) c[i][j][q] = 0.f;
    uint4 pa[2], pb[2];
    #pragma unroll
    for (int i = 0; i < 2; i++) {
        int idx = tid + i * 256;
        int r = idx >> 2, seg = idx & 3;
        pa[i] = *(const uint4*)(A + (size_t)(rowBase + r) * HC + seg * 8);
        uint4 vb = make_uint4(0, 0, 0, 0);
        int gn = colBase + r;
        if (gn < N) vb = *(const uint4*)(B + (size_t)gn * HC + seg * 8);
        pb[i] = vb;
    }
    for (int k0 = 0; k0 < HC; k0 += BGK) {
        #pragma unroll
        for (int i = 0; i < 2; i++) {
            int idx = tid + i * 256;
            int r = idx >> 2, seg = idx & 3;
            *(uint4*)(As + r * SSTR + seg * 8) = pa[i];
            *(uint4*)(Bs + r * SSTR + seg * 8) = pb[i];
        }
        __syncthreads();
        if (k0 + BGK < HC) {
            #pragma unroll
            for (int i = 0; i < 2; i++) {
                int idx = tid + i * 256;
                int r = idx >> 2, seg = idx & 3;
                pa[i] = *(const uint4*)(A + (size_t)(rowBase + r) * HC + k0 + BGK + seg * 8);
                uint4 vb = make_uint4(0, 0, 0, 0);
                int gn = colBase + r;
                if (gn < N) vb = *(const uint4*)(B + (size_t)gn * HC + k0 + BGK + seg * 8);
                pb[i] = vb;
            }
        }
        MMA_STEP(As, Bs, SSTR, 0, 0, c)
        MMA_STEP(As, Bs, SSTR, 0, 16, c)
        __syncthreads();
    }
    float lsp = 0.f, lxo = 0.f;
    #pragma unroll
    for (int mt = 0; mt < 2; mt++) {
        int r0 = rowBase + wm * 32 + mt * 16 + (lane >> 2);
        int ob0 = trip[r0 * 3 + 2];
        int ob1 = trip[(r0 + 8) * 3 + 2];
        #pragma unroll
        for (int nt = 0; nt < 8; nt++) {
            int col = colBase + wn * 64 + nt * 8 + ((lane & 3) << 1);
            if (col < N) {
                #pragma unroll
                for (int half = 0; half < 2; half++) {
                    int row = r0 + half * 8;
                    int ob = half ? ob1 : ob0;
                    float x0 = c[mt][nt][half * 2 + 0];
                    float x1 = c[mt][nt][half * 2 + 1];
                    float s0, p0, s1, p1;
                    sig_sp(x0, s0, p0);
                    sig_sp(x1, s1, p1);
                    __stcs((float2*)(Cf + (size_t)row * N + col), make_float2(s0, s1));
                    lsp += p0 + p1;
                    if (col == ob) lxo += x0;
                    if (col + 1 == ob) lxo += x1;
                }
            }
        }
    }
    float bs = blockReduceSum(lsp);
    float bx = blockReduceSum(lxo);
    if (tid == 0) {
        atomicAdd(&acc[0], (double)bs);
        atomicAdd(&acc[1], (double)bx);
        __threadfence();
        int old = atomicAdd(done, 1);
        if (old == nblocks - 1 && write_final) {
            double a0 = atomicAdd(&acc[0], 0.0);
            double a1 = atomicAdd(&acc[1], 0.0);
            double a2 = atomicAdd(&acc[2], 0.0);
            Cf[(size_t)NBC * N_ENTC]     = (float)(a2 / (double)(NBC * HC));
            Cf[(size_t)NBC * N_ENTC + 1] = (float)((a0 - a1) /
                                                   ((double)NBC * (double)N_ENTC));
        }
    }
}

// ---------------- fused pre+aln (pipelined, 2 blocks/SM) ----------------
#define PREALN_LOAD(i, k0v, dst)                                                     \
    {                                                                                 \
        int idx = tid + (i) * 256;                                                    \
        int seg = idx & 3;                                                            \
        int gr = rowBase + lr[i];                                                     \
        int kc = (k0v) + seg * 8;                                                     \
        uint4 va = make_uint4(0, 0, 0, 0);                                            \
        if (lv[i]) {                                                                  \
            if ((k0v) < 128) {                                                        \
                va = *(const uint4*)(g_aggb + (size_t)gr * HC + kc);                  \
            } else if ((k0v) < 256) {                                                 \
                if (lm[i]) va = *(const uint4*)(g_entb + (size_t)gr * HC + kc - 128); \
            } else {                                                                  \
                if (!lm[i]) va = *(const uint4*)(g_entb + (size_t)gr * HC + kc - 256);\
            }                                                                         \
        }                                                                             \
        dst = va;                                                                     \
    }

__global__ __launch_bounds__(256, 2)
void k_prealn(const float* __restrict__ bal, const int* __restrict__ deg, int M) {
    extern __shared__ __nv_bfloat16 sm[];
    __nv_bfloat16* As = sm;
    __nv_bfloat16* Bs = sm + BGM * SSTR;
    __nv_bfloat16* Xs = sm + 2 * BGM * SSTR;
    int tid = threadIdx.x, lane = tid & 31, wid = tid >> 5;
    int wm = wid & 3, wn = wid >> 2;
    int rowBase = blockIdx.x * BGM;
    int lr[2]; bool lv[2], lm[2];
    #pragma unroll
    for (int i = 0; i < 2; i++) {
        int idx = tid + i * 256;
        lr[i] = idx >> 2;
        int gr = rowBase + lr[i];
        lv[i] = gr < M;
        lm[i] = lv[i] && (deg[lv[i] ? gr : 0] > 0);
    }
    float c[2][8][4];
    #pragma unroll
    for (int i = 0; i < 2; i++)
        #pragma unroll
        for (int j = 0; j < 8; j++)
            #pragma unroll
            for (int q = 0; q < 4; q++) c[i][j][q] = 0.f;
    uint4 pa[2], pb[2];
    #pragma unroll
    for (int i = 0; i < 2; i++) {
        PREALN_LOAD(i, 0, pa[i])
        int idx = tid + i * 256;
        int r = idx >> 2, seg = idx & 3;
        pb[i] = *(const uint4*)(g_B3 + (size_t)r * KPRE + seg * 8);
    }
    for (int k0 = 0; k0 < KPRE; k0 += BGK) {
        #pragma unroll
        for (int i = 0; i < 2; i++) {
            int idx = tid + i * 256;
            int r = idx >> 2, seg = idx & 3;
            *(uint4*)(As + r * SSTR + seg * 8) = pa[i];
            *(uint4*)(Bs + r * SSTR + seg * 8) = pb[i];
        }
        __syncthreads();
        if (k0 + BGK < KPRE) {
            #pragma unroll
            for (int i = 0; i < 2; i++) {
                PREALN_LOAD(i, k0 + BGK, pa[i])
                int idx = tid + i * 256;
                int r = idx >> 2, seg = idx & 3;
                pb[i] = *(const uint4*)(g_B3 + (size_t)r * KPRE + k0 + BGK + seg * 8);
            }
        }
        MMA_STEP(As, Bs, SSTR, 0, 0, c)
        MMA_STEP(As, Bs, SSTR, 0, 16, c)
        __syncthreads();
    }
    #pragma unroll
    for (int mt = 0; mt < 2; mt++) {
        #pragma unroll
        for (int nt = 0; nt < 8; nt++) {
            int colL = wn * 64 + nt * 8 + ((lane & 3) << 1);
            #pragma unroll
            for (int half = 0; half < 2; half++) {
                int rowL = wm * 32 + mt * 16 + (lane >> 2) + half * 8;
                float v0 = c[mt][nt][half * 2 + 0];
                float v1 = c[mt][nt][half * 2 + 1];
                v0 = (v0 >= 0.f) ? v0 : v0 * SLOPE;
                v1 = (v1 >= 0.f) ? v1 : v1 * SLOPE;
                __nv_bfloat162 bv(__float2bfloat16(v0), __float2bfloat16(v1));
                *(__nv_bfloat162*)(Xs + rowL * XSTR + colL) = bv;
                int grow = rowBase + rowL;
                if (grow < M)
                    *(__nv_bfloat162*)(g_prebf + (size_t)grow * HC + colL) = bv;
            }
        }
    }
    __syncthreads();
    float c2[2][8][4];
    #pragma unroll
    for (int i = 0; i < 2; i++)
        #pragma unroll
        for (int j = 0; j < 8; j++)
            #pragma unroll
            for (int q = 0; q < 4; q++) c2[i][j][q] = 0.f;
    #pragma unroll
    for (int i = 0; i < 2; i++) {
        int idx = tid + i * 256;
        int r = idx >> 2, seg = idx & 3;
        pb[i] = *(const uint4*)(g_walb + (size_t)r * HC + seg * 8);
    }
    for (int k0 = 0; k0 < HC; k0 += BGK) {
        #pragma unroll
        for (int i = 0; i < 2; i++) {
            int idx = tid + i * 256;
            int r = idx >> 2, seg = idx & 3;
            *(uint4*)(Bs + r * SSTR + seg * 8) = pb[i];
        }
        __syncthreads();
        if (k0 + BGK < HC) {
            #pragma unroll
            for (int i = 0; i < 2; i++) {
                int idx = tid + i * 256;
                int r = idx >> 2, seg = idx & 3;
                pb[i] = *(const uint4*)(g_walb + (size_t)r * HC + k0 + BGK + seg * 8);
            }
        }
        MMA_STEP(Xs, Bs, XSTR, k0, 0, c2)
        MMA_STEP(Xs, Bs, XSTR, k0, 16, c2)
        __syncthreads();
    }
    #pragma unroll
    for (int mt = 0; mt < 2; mt++) {
        #pragma unroll
        for (int nt = 0; nt < 8; nt++) {
            int colL = wn * 64 + nt * 8 + ((lane & 3) << 1);
            float b0 = bal[colL], b1 = bal[colL + 1];
            #pragma unroll
            for (int half = 0; half < 2; half++) {
                int grow = rowBase + wm * 32 + mt * 16 + (lane >> 2) + half * 8;
                if (grow < M) {
                    __nv_bfloat162 bv(__float2bfloat16(c2[mt][nt][half * 2 + 0] + b0),
                                      __float2bfloat16(c2[mt][nt][half * 2 + 1] + b1));
                    *(__nv_bfloat162*)(g_alnbf + (size_t)grow * HC + colL) = bv;
                }
            }
        }
    }
}

// ---------------- fused softmax+rpath+giall (pipelined, 2 blocks/SM) ----------------
__global__ __launch_bounds__(256, 2)
void k_rpgi(const float* __restrict__ part, const float* __restrict__ Amat,
            const float* __restrict__ bih, float* __restrict__ giall) {
    extern __shared__ __nv_bfloat16 sm[];
    __nv_bfloat16* As = sm;
    __nv_bfloat16* Bs = sm + BGM * SSTR;
    __nv_bfloat16* Xs = sm + 2 * BGM * SSTR;
    int tid = threadIdx.x, lane = tid & 31, wid = tid >> 5;
    int wm = wid & 3, wn = wid >> 2;
    int rowBase = blockIdx.x * BGM;
    uint4 pa[2], pb[2];
    if (blockIdx.x < 64) {
        for (int rr = wid; rr < BGM; rr += 8) {
            int grow = rowBase + rr;
            int t = grow >> 10, b = grow & 1023;
            const float* prow = part + (size_t)b * (NTC * NRELC) + t * NRELC;
            const float* arow = Amat + (size_t)b * NRELC;
            float xv[15];
            float m = -3.402823e38f;
            #pragma unroll
            for (int i = 0; i < 15; i++) {
                int cc = lane + i * 32;
                float x = -3.402823e38f;
                if (cc < NRELC) {
                    float val = prow[cc] * arow[cc];
                    x = (val == 0.f) ? -1e9f : val;
                }
                xv[i] = x;
                m = fmaxf(m, x);
            }
            #pragma unroll
            for (int o = 16; o > 0; o >>= 1) m = fmaxf(m, __shfl_xor_sync(0xffffffffu, m, o));
            float s = 0.f;
            float ev[15];
            #pragma unroll
            for (int i = 0; i < 15; i++) {
                int cc = lane + i * 32;
                float e = (cc < NRELC) ? __expf(xv[i] - m) : 0.f;
                ev[i] = e;
                s += e;
            }
            #pragma unroll
            for (int o = 16; o > 0; o >>= 1) s += __shfl_xor_sync(0xffffffffu, s, o);
            float inv = 1.f / s;
            __nv_bfloat16* orow = g_attnb + (size_t)grow * KPAD;
            #pragma unroll
            for (int i = 0; i < 15; i++) {
                int cc = lane + i * 32;
                if (cc < NRELC) orow[cc] = __float2bfloat16(ev[i] * inv);
            }
        }
        __syncthreads();
        float c[2][8][4];
        #pragma unroll
        for (int i = 0; i < 2; i++)
            #pragma unroll
            for (int j = 0; j < 8; j++)
                #pragma unroll
                for (int q = 0; q < 4; q++) c[i][j][q] = 0.f;
        #pragma unroll
        for (int i = 0; i < 2; i++) {
            int idx = tid + i * 256;
            int r = idx >> 2, seg = idx & 3;
            pa[i] = *(const uint4*)(g_attnb + (size_t)(rowBase + r) * KPAD + seg * 8);
            pb[i] = *(const uint4*)(g_mrelTb + (size_t)r * KPAD + seg * 8);
        }
        for (int k0 = 0; k0 < KPAD; k0 += BGK) {
            #pragma unroll
            for (int i = 0; i < 2; i++) {
                int idx = tid + i * 256;
                int r = idx >> 2, seg = idx & 3;
                *(uint4*)(As + r * SSTR + seg * 8) = pa[i];
                *(uint4*)(Bs + r * SSTR + seg * 8) = pb[i];
            }
            __syncthreads();
            if (k0 + BGK < KPAD) {
                #pragma unroll
                for (int i = 0; i < 2; i++) {
                    int idx = tid + i * 256;
                    int r = idx >> 2, seg = idx & 3;
                    pa[i] = *(const uint4*)(g_attnb + (size_t)(rowBase + r) * KPAD + k0 + BGK + seg * 8);
                    pb[i] = *(const uint4*)(g_mrelTb + (size_t)r * KPAD + k0 + BGK + seg * 8);
                }
            }
            MMA_STEP(As, Bs, SSTR, 0, 0, c)
            MMA_STEP(As, Bs, SSTR, 0, 16, c)
            __syncthreads();
        }
        #pragma unroll
        for (int mt = 0; mt < 2; mt++)
            #pragma unroll
            for (int nt = 0; nt < 8; nt++) {
                int colL = wn * 64 + nt * 8 + ((lane & 3) << 1);
                #pragma unroll
                for (int half = 0; half < 2; half++) {
                    int rowL = wm * 32 + mt * 16 + (lane >> 2) + half * 8;
                    __nv_bfloat162 bv(__float2bfloat16(c[mt][nt][half * 2 + 0]),
                                      __float2bfloat16(c[mt][nt][half * 2 + 1]));
                    *(__nv_bfloat162*)(Xs + rowL * XSTR + colL) = bv;
                }
            }
    } else {
        for (int i = tid; i < BGM * (HC / 8); i += 256) {
            int r = i / (HC / 8), seg = i % (HC / 8);
            *(uint4*)(Xs + r * XSTR + seg * 8) =
                *(const uint4*)(g_Xb + (size_t)(rowBase + r) * HC + seg * 8);
        }
    }
    __syncthreads();
    for (int nb = 0; nb < 3; nb++) {
        float c2[2][8][4];
        #pragma unroll
        for (int i = 0; i < 2; i++)
            #pragma unroll
            for (int j = 0; j < 8; j++)
                #pragma unroll
                for (int q = 0; q < 4; q++) c2[i][j][q] = 0.f;
        #pragma unroll
        for (int i = 0; i < 2; i++) {
            int idx = tid + i * 256;
            int r = idx >> 2, seg = idx & 3;
            pb[i] = *(const uint4*)(g_wihb + (size_t)(nb * 128 + r) * HC + seg * 8);
        }
        for (int k0 = 0; k0 < HC; k0 += BGK) {
            #pragma unroll
            for (int i = 0; i < 2; i++) {
                int idx = tid + i * 256;
                int r = idx >> 2, seg = idx & 3;
                *(uint4*)(Bs + r * SSTR + seg * 8) = pb[i];
            }
            __syncthreads();
            if (k0 + BGK < HC) {
                #pragma unroll
                for (int i = 0; i < 2; i++) {
                    int idx = tid + i * 256;
                    int r = idx >> 2, seg = idx & 3;
                    pb[i] = *(const uint4*)(g_wihb + (size_t)(nb * 128 + r) * HC + k0 + BGK + seg * 8);
                }
            }
            MMA_STEP(Xs, Bs, XSTR, k0, 0, c2)
            MMA_STEP(Xs, Bs, XSTR, k0, 16, c2)
            __syncthreads();
        }
        #pragma unroll
        for (int mt = 0; mt < 2; mt++)
            #pragma unroll
            for (int nt = 0; nt < 8; nt++) {
                int colL = wn * 64 + nt * 8 + ((lane & 3) << 1);
                int col = nb * 128 + colL;
                float b0 = bih[col], b1 = bih[col + 1];
                #pragma unroll
                for (int half = 0; half < 2; half++) {
                    int row = rowBase + wm * 32 + mt * 16 + (lane >> 2) + half * 8;
                    *(float2*)(giall + (size_t)row * H3C + col) =
                        make_float2(c2[mt][nt][half * 2 + 0] + b0,
                                    c2[mt][nt][half * 2 + 1] + b1);
                }
            }
    }
}

// ---------------- fused mapped_rel ----------------
__global__ __launch_bounds__(256)
void k_mrel(const float* __restrict__ rel, const float* __restrict__ Wm1T,
            const float* __restrict__ Wm2T, const float* __restrict__ bm1,
            const float* __restrict__ bm2, float* __restrict__ mrel,
            float* __restrict__ mrelT) {
    __shared__ float rels[10][128];
    __shared__ float p1s[10][256];
    int tid = threadIdx.x;
    int r0 = blockIdx.x * 10;
    for (int i = tid; i < 10 * 128; i += 256)
        rels[i >> 7][i & 127] = rel[(r0 + (i >> 7)) * 128 + (i & 127)];
    __syncthreads();
    {
        int j2 = tid;
        float a[10];
        #pragma unroll
        for (int r = 0; r < 10; r++) a[r] = 0.f;
        for (int k = 0; k < 128; k++) {
            float w = Wm1T[k * 256 + j2];
            #pragma unroll
            for (int r = 0; r < 10; r++) a[r] = fmaf(rels[r][k], w, a[r]);
        }
        float b = bm1[j2];
        #pragma unroll
        for (int r = 0; r < 10; r++) p1s[r][j2] = a[r] + b;
    }
    __syncthreads();
    {
        int j = tid & 127, half = tid >> 7;
        float a[5];
        #pragma unroll
        for (int r = 0; r < 5; r++) a[r] = 0.f;
        for (int k = 0; k < 256; k++) {
            float w = Wm2T[k * 128 + j];
            #pragma unroll
            for (int r = 0; r < 5; r++) a[r] = fmaf(p1s[half * 5 + r][k], w, a[r]);
        }
        float b = bm2[j];
        #pragma unroll
        for (int r = 0; r < 5; r++) {
            int row = r0 + half * 5 + r;
            float v = a[r] + b;
            mrel[row * 128 + j] = v;
            mrelT[j * MT_STR + row] = v;
            g_mrelTb[j * KPAD + row] = __float2bfloat16(v);
        }
    }
}

__global__ __launch_bounds__(128)
void k_qa_amat(const float* __restrict__ mrel, const int* __restrict__ trip,
               const float* __restrict__ WatT, const float* __restrict__ bat,
               const float* __restrict__ mrelT, float* __restrict__ qrel,
               float* __restrict__ Amat) {
    __shared__ float q[4][128];
    __shared__ float qa[4][128];
    int j = threadIdx.x;
    int r0 = blockIdx.x * 4;
    #pragma unroll
    for (int r = 0; r < 4; r++) {
        float v = mrel[(size_t)trip[(r0 + r) * 3 + 1] * HC + j];
        q[r][j] = v;
        qrel[(r0 + r) * 128 + j] = v;
        g_Xb[(size_t)(NTC * NBC + r0 + r) * HC + j] = __float2bfloat16(v);
    }
    __syncthreads();
    {
        float a[4] = {0.f, 0.f, 0.f, 0.f};
        for (int k = 0; k < 128; k++) {
            float w = WatT[k * 128 + j];
            #pragma unroll
            for (int r = 0; r < 4; r++) a[r] = fmaf(q[r][k], w, a[r]);
        }
        float b = bat[j];
        #pragma unroll
        for (int r = 0; r < 4; r++) qa[r][j] = a[r] + b;
    }
    __syncthreads();
    float a[4][4];
    #pragma unroll
    for (int r = 0; r < 4; r++)
        #pragma unroll
        for (int t = 0; t < 4; t++) a[r][t] = 0.f;
    for (int k = 0; k < 128; k++) {
        float m0 = mrelT[k * MT_STR + j];
        float m1 = mrelT[k * MT_STR + j + 128];
        float m2 = mrelT[k * MT_STR + j + 256];
        float m3 = mrelT[k * MT_STR + j + 384];
        #pragma unroll
        for (int r = 0; r < 4; r++) {
            float qv = qa[r][k];
            a[r][0] = fmaf(qv, m0, a[r][0]);
            a[r][1] = fmaf(qv, m1, a[r][1]);
            a[r][2] = fmaf(qv, m2, a[r][2]);
            a[r][3] = fmaf(qv, m3, a[r][3]);
        }
    }
    #pragma unroll
    for (int r = 0; r < 4; r++)
        #pragma unroll
        for (int t = 0; t < 4; t++) {
            int n = j + t * 128;
            if (n < NRELC) Amat[(size_t)(r0 + r) * NRELC + n] = a[r][t];
        }
}

// ---------------- mega GRU kernel ----------------
__global__ __launch_bounds__(384)
void k_gru_all(const float* __restrict__ giall, const float* __restrict__ whhT,
               const float* __restrict__ bhh, const float* __restrict__ qrel,
               const float* __restrict__ Wh1T, const float* __restrict__ Wh2T,
               const float* __restrict__ bh1, const float* __restrict__ bh2,
               const int* __restrict__ trip, const float* __restrict__ WalT,
               const float* __restrict__ bal, double* acc) {
    extern __shared__ float swhh[];
    __shared__ float hs[8][128];
    __shared__ float asg[8][384];
    __shared__ float qs[8][128];
    __shared__ float ps[8][128];
    int tid = threadIdx.x;
    int j = tid & 127;
    int g = tid >> 7;
    int r0 = blockIdx.x * 8;

    for (int i = tid; i < HC * H3C; i += 384) swhh[i] = whhT[i];
    for (int i = tid; i < 8 * 128; i += 384) hs[i >> 7][i & 127] = 0.f;
    __syncthreads();

    for (int t = 0; t < NTC; t++) {
        {
            float a[8];
            #pragma unroll
            for (int r = 0; r < 8; r++) a[r] = 0.f;
            for (int k = 0; k < 128; k++) {
                float w = swhh[k * H3C + tid];
                #pragma unroll
                for (int r = 0; r < 8; r++) a[r] = fmaf(hs[r][k], w, a[r]);
            }
            #pragma unroll
            for (int r = 0; r < 8; r++) asg[r][tid] = a[r];
        }
        __syncthreads();
        if (tid < 128) {
            float br = bhh[j], bz = bhh[128 + j], bn = bhh[256 + j];
            const float* gi = giall + (size_t)t * NBC * H3C;
            #pragma unroll
            for (int r = 0; r < 8; r++) {
                size_t gx = (size_t)(r0 + r) * H3C;
                float rr = sigm(gi[gx + j] + asg[r][j] + br);
                float zz = sigm(gi[gx + 128 + j] + asg[r][128 + j] + bz);
                float nn = tanhf(gi[gx + 256 + j] + rr * (asg[r][256 + j] + bn));
                hs[r][j] = (1.f - zz) * nn + zz * hs[r][j];
            }
        }
        __syncthreads();
    }

    for (int i = tid; i < 8 * 128; i += 384)
        qs[i >> 7][i & 127] = qrel[(r0 + (i >> 7)) * 128 + (i & 127)];
    __syncthreads();

    for (int r = g; r < 8; r += 3) {
        float a = 0.f;
        for (int k = 0; k < 128; k++) a = fmaf(qs[r][k], Wh1T[k * 128 + j], a);
        ps[r][j] = a + bh1[j];
    }
    __syncthreads();
    float predv[3];
    int nmine = 0;
    for (int r = g; r < 8; r += 3) {
        float a = 0.f;
        for (int k = 0; k < 128; k++) a = fmaf(ps[r][k], Wh2T[k * 128 + j], a);
        predv[nmine++] = 0.1f * (a + bh2[j]) + qs[r][j];
    }
    __syncthreads();
    {
        int m = 0;
        for (int r = g; r < 8; r += 3) ps[r][j] = predv[m++];
    }
    __syncthreads();
    {
        float msum = 0.f;
        for (int r = g; r < 8; r += 3) {
            float d = ps[r][j] - hs[r][j];
            msum += d * d;
        }
        float bsum = blockReduceSum(msum);
        if (tid == 0) atomicAdd(&acc[2], (double)bsum);
    }
    __syncthreads();
    {
        float a[8];
        #pragma unroll
        for (int r = 0; r < 8; r++) a[r] = 0.f;
        for (int k = 0; k < 128; k++) {
            float w = swhh[k * H3C + tid];
            #pragma unroll
            for (int r = 0; r < 8; r++) a[r] = fmaf(ps[r][k], w, a[r]);
        }
        #pragma unroll
        for (int r = 0; r < 8; r++) asg[r][tid] = a[r];
    }
    __syncthreads();
    if (tid < 128) {
        float br = bhh[j], bz = bhh[128 + j], bn = bhh[256 + j];
        const float* gi = giall + (size_t)NTC * NBC * H3C;
        #pragma unroll
        for (int r = 0; r < 8; r++) {
            size_t gx = (size_t)(r0 + r) * H3C;
            float rr = sigm(gi[gx + j] + asg[r][j] + br);
            float zz = sigm(gi[gx + 128 + j] + asg[r][128 + j] + bz);
            float nn = tanhf(gi[gx + 256 + j] + rr * (asg[r][256 + j] + bn));
            hs[r][j] = (1.f - zz) * nn + zz * ps[r][j];
        }
    }
    __syncthreads();
    for (int i = tid; i < 8 * 128; i += 384) {
        int r = i >> 7, c = i & 127;
        int row = trip[(r0 + r) * 3 + 0];
        qs[r][c] = __bfloat162float(g_prebf[(size_t)row * HC + c]);
    }
    __syncthreads();
    for (int r = g; r < 8; r += 3) {
        float a = 0.f;
        for (int k = 0; k < 128; k++) a = fmaf(qs[r][k], WalT[k * 128 + j], a);
        float v = (a + bal[j]) * hs[r][j];
        g_svecb[(r0 + r) * 128 + j] = __float2bfloat16(v);
    }
}

// ---------------- host ----------------
extern "C" void kernel_launch(void* const* d_in, const int* in_sizes, int n_in,
                              void* d_out, int out_size) {
    const float* ent  = (const float*)d_in[0];
    const float* rel  = (const float*)d_in[1];
    const float* Wn   = (const float*)d_in[2];
    const float* Wl   = (const float*)d_in[3];
    const float* Wev  = (const float*)d_in[4];
    const float* wih  = (const float*)d_in[5];
    const float* whh  = (const float*)d_in[6];
    const float* bih  = (const float*)d_in[7];
    const float* bhh  = (const float*)d_in[8];
    const float* Wm1  = (const float*)d_in[9];
    const float* bm1  = (const float*)d_in[10];
    const float* Wm2  = (const float*)d_in[11];
    const float* bm2  = (const float*)d_in[12];
    const float* Wh1  = (const float*)d_in[13];
    const float* bh1  = (const float*)d_in[14];
    const float* Wh2  = (const float*)d_in[15];
    const float* bh2  = (const float*)d_in[16];
    const float* Wal  = (const float*)d_in[17];
    const float* bal  = (const float*)d_in[18];
    const float* Wat  = (const float*)d_in[19];
    const float* bat  = (const float*)d_in[20];
    const float* part = (const float*)d_in[21];
    const int* esrc = (const int*)d_in[22];
    const int* edst = (const int*)d_in[23];
    const int* etyp = (const int*)d_in[24];
    const int* trip = (const int*)d_in[25];
    float* out = (float*)d_out;

    void* basep = nullptr;
    cudaGetSymbolAddress(&basep, d_buf);
    float* F = (float*)basep;
    __nv_bfloat16 *pSvecb, *pAlnb;
    { void* p; cudaGetSymbolAddress(&p, g_svecb); pSvecb = (__nv_bfloat16*)p; }
    { void* p; cudaGetSymbolAddress(&p, g_alnbf); pAlnb  = (__nv_bfloat16*)p; }

    float* mrel   = F + O_MREL;
    float* mrelT  = F + O_MRELT;
    float* qrel   = F + O_QREL;
    float* Amat   = F + O_AMAT;
    float* giall  = F + O_GIALL;
    float* whhT   = F + O_WHHT;
    float* Wh1T   = F + O_WH1T;
    float* Wh2T   = F + O_WH2T;
    float* WatT   = F + O_WATT;
    float* WalT   = F + O_WALT;
    float* Wm1T   = F + O_WM1T;
    float* Wm2T   = F + O_WM2T;
    double* acc   = (double*)(F + O_ACC);
    int* deg      = (int*)(F + O_INT);
    int* rowptr   = deg + N_ENTC;
    int* cursor   = rowptr + N_ENTC + 1;
    int* csr      = cursor + N_ENTC;
    int* bsums    = csr + NEC;
    int* done     = bsums + 32;

    const int FUSED_SMEM = (2 * BGM * SSTR + BGM * XSTR) * 2;  // 55296 B
    const int GRU_SMEM = HC * H3C * 4;                          // 196608 B
    static bool s_init = false;
    static cudaStream_t sB = 0;
    static cudaEvent_t evF = 0, evB = 0;
    if (!s_init) {
        cudaFuncSetAttribute(k_prealn, cudaFuncAttributeMaxDynamicSharedMemorySize, FUSED_SMEM);
        cudaFuncSetAttribute(k_rpgi,   cudaFuncAttributeMaxDynamicSharedMemorySize, FUSED_SMEM);
        cudaFuncSetAttribute(k_gru_all, cudaFuncAttributeMaxDynamicSharedMemorySize, GRU_SMEM);
        cudaStreamCreateWithFlags(&sB, cudaStreamNonBlocking);
        cudaEventCreateWithFlags(&evF, cudaEventDisableTiming);
        cudaEventCreateWithFlags(&evB, cudaEventDisableTiming);
        s_init = true;
    }

    k_init<<<640, 256>>>(Wn, Wl, Wev, wih, whh, Wal, Wh1, Wh2, Wat, Wm1, Wm2, rel,
                         deg, cursor, acc, done, F);
    cudaEventRecord(evF, 0);
    cudaStreamWaitEvent(sB, evF, 0);

    // ---- chain B (relation path) on sB ----
    k_mrel<<<46, 256, 0, sB>>>(rel, Wm1T, Wm2T, bm1, bm2, mrel, mrelT);
    k_qa_amat<<<256, 128, 0, sB>>>(mrel, trip, WatT, bat, mrelT, qrel, Amat);
    k_rpgi<<<(NTC + 1) * NBC / BGM, 256, FUSED_SMEM, sB>>>(part, Amat, bih, giall);
    cudaEventRecord(evB, sB);

    // ---- chain A (entity path) on default stream ----
    k_count_entcvt<<<(N_ENTC * HC + 255) / 256, 256>>>(edst, deg, ent);
    k_scanA<<<(N_ENTC + 1023) / 1024, 1024>>>(deg, rowptr, bsums);
    k_scanB<<<1, 1024>>>(rowptr, bsums, (N_ENTC + 1023) / 1024);
    k_fill<<<(NEC + 255) / 256, 256>>>(edst, esrc, etyp, rowptr, cursor, csr);
    k_aggregate<<<N_ENTC, 64>>>(rowptr, csr);
    k_prealn<<<(N_ENTC + BGM - 1) / BGM, 256, FUSED_SMEM>>>(bal, deg, N_ENTC);

    // ---- join ----
    cudaStreamWaitEvent(0, evB, 0);
    k_gru_all<<<128, 384, GRU_SMEM>>>(giall, whhT, bhh, qrel, Wh1T, Wh2T, bh1, bh2,
                                      trip, WalT, bal, acc);
    {
        dim3 g((N_ENTC + BGN - 1) / BGN, NBC / BGM);
        int nblocks = g.x * g.y;
        int wf = (out_size >= NBC * N_ENTC + 2) ? 1 : 0;
        k_score<<<g, 256>>>(pSvecb, pAlnb, out, trip, acc, done, nblocks, wf,
                            NBC, N_ENTC);
    }
}

// round 15
// speedup vs baseline: 1.0101x; 1.0101x over previous
#include <cuda_runtime.h>
#include <cuda_bf16.h>
#include <stdint.h>
#include <math.h>

#define N_ENTC 20000
#define NRELC  460
#define HC     128
#define NEC    400000
#define NBC    1024
#define NTC    8
#define H3C    384
#define SLOPE  0.22916666666666666f
#define KPRE   384
#define KPAD   480
#define MT_STR 512

// ---------------- fp32 scratch ----------------
constexpr size_t O_MREL  = 0;
constexpr size_t O_MRELT = O_MREL + (size_t)NRELC * HC;
constexpr size_t O_QREL  = O_MRELT + (size_t)HC * MT_STR;
constexpr size_t O_AMAT  = O_QREL + (size_t)NBC * HC;
constexpr size_t O_GIALL = O_AMAT + (size_t)NBC * NRELC;
constexpr size_t O_WHHT  = O_GIALL + (size_t)(NTC + 1) * NBC * H3C;
constexpr size_t O_WH1T  = O_WHHT + 49152;
constexpr size_t O_WH2T  = O_WH1T + 16384;
constexpr size_t O_WATT  = O_WH2T + 16384;
constexpr size_t O_WALT  = O_WATT + 16384;
constexpr size_t O_WM1T  = O_WALT + 16384;
constexpr size_t O_WM2T  = O_WM1T + 32768;
constexpr size_t O_ACC_  = O_WM2T + 32768;
constexpr size_t O_ACC   = (O_ACC_ + 1) & ~(size_t)1;
constexpr size_t O_INT   = O_ACC + 8;
constexpr size_t N_INTS  = (size_t)N_ENTC + (N_ENTC + 1) + N_ENTC + NEC + 64;
constexpr size_t TOTALF  = O_INT + N_INTS;
__device__ __align__(16) float d_buf[TOTALF];

// ---------------- bf16 scratch ----------------
__device__ __align__(16) __nv_bfloat16 g_aggb[(size_t)N_ENTC * HC];
__device__ __align__(16) __nv_bfloat16 g_B3[HC * KPRE];
__device__ __align__(16) __nv_bfloat16 g_entb[(size_t)N_ENTC * HC];
__device__ __align__(16) __nv_bfloat16 g_relb[NRELC * HC];
__device__ __align__(16) __nv_bfloat16 g_prebf[(size_t)N_ENTC * HC];
__device__ __align__(16) __nv_bfloat16 g_alnbf[(size_t)N_ENTC * HC];
__device__ __align__(16) __nv_bfloat16 g_walb[HC * HC];
__device__ __align__(16) __nv_bfloat16 g_wihb[H3C * HC];
__device__ __align__(16) __nv_bfloat16 g_mrelTb[HC * KPAD];
__device__ __align__(16) __nv_bfloat16 g_Xb[(size_t)(NTC + 1) * NBC * HC];
__device__ __align__(16) __nv_bfloat16 g_attnb[(size_t)NTC * NBC * KPAD];
__device__ __align__(16) __nv_bfloat16 g_svecb[(size_t)NBC * HC];

// ---------------- cp.async helpers ----------------
__device__ __forceinline__ void cpa16(void* sdst, const void* gsrc) {
    uint32_t s = (uint32_t)__cvta_generic_to_shared(sdst);
    asm volatile("cp.async.ca.shared.global [%0], [%1], 16;\n" :: "r"(s), "l"(gsrc));
}
__device__ __forceinline__ void cpa16z(void* sdst, const void* gsrc, bool pred) {
    uint32_t s = (uint32_t)__cvta_generic_to_shared(sdst);
    int sz = pred ? 16 : 0;
    asm volatile("cp.async.ca.shared.global [%0], [%1], 16, %2;\n"
                 :: "r"(s), "l"(gsrc), "r"(sz));
}
#define CP_COMMIT() asm volatile("cp.async.commit_group;\n" ::: "memory")
#define CP_WAIT1()  asm volatile("cp.async.wait_group 1;\n" ::: "memory")
#define CP_WAIT0()  asm volatile("cp.async.wait_group 0;\n" ::: "memory")

// ---------------- reductions ----------------
__device__ __forceinline__ float blockReduceSum(float v) {
    __shared__ float sh[32];
    int tid = threadIdx.x;
    __syncthreads();
    #pragma unroll
    for (int o = 16; o > 0; o >>= 1) v += __shfl_xor_sync(0xffffffffu, v, o);
    if ((tid & 31) == 0) sh[tid >> 5] = v;
    __syncthreads();
    float r = 0.f;
    if (tid < 32) {
        int nw = (blockDim.x + 31) >> 5;
        r = (tid < nw) ? sh[tid] : 0.f;
        #pragma unroll
        for (int o = 16; o > 0; o >>= 1) r += __shfl_xor_sync(0xffffffffu, r, o);
    }
    return r;
}

__device__ __forceinline__ void sig_sp(float x, float& sig, float& sp) {
    float ax = fabsf(x);
    if (ax < 0.5f) {
        float x2 = x * x;
        sig = 0.5f + x * (0.25f + x2 * (-0.0208333333f + x2 * 0.0020833333f));
        sp  = 0.69314718f + 0.5f * x
            + x2 * (0.125f + x2 * (-0.0052083333f + x2 * 0.00034722222f));
    } else {
        float e = __expf(-ax);
        sig = (x >= 0.f) ? 1.f / (1.f + e) : e / (1.f + e);
        sp  = fmaxf(x, 0.f) + __logf(1.f + e);
    }
}
__device__ __forceinline__ float sigm(float x) { return 1.f / (1.f + __expf(-x)); }

// ---------------- init ----------------
__global__ void k_init(const float* __restrict__ Wn, const float* __restrict__ Wl,
                       const float* __restrict__ Wev, const float* __restrict__ wih,
                       const float* __restrict__ whh, const float* __restrict__ Wal,
                       const float* __restrict__ Wh1, const float* __restrict__ Wh2,
                       const float* __restrict__ Wat, const float* __restrict__ Wm1,
                       const float* __restrict__ Wm2, const float* __restrict__ rel,
                       int* deg, int* cursor, double* acc, int* done, float* F) {
    int i = blockIdx.x * blockDim.x + threadIdx.x;  // grid 640*256
    if (i < N_ENTC) { deg[i] = 0; cursor[i] = 0; }
    if (i == 0) { acc[0] = 0.0; acc[1] = 0.0; acc[2] = 0.0; done[0] = 0; }
    if (i < HC * KPRE) {
        int n = i / KPRE, k = i % KPRE;
        float v = (k < 128) ? Wn[k * 128 + n]
                : (k < 256) ? Wl[(k - 128) * 128 + n]
                            : Wev[(k - 256) * 128 + n];
        g_B3[i] = __float2bfloat16(v);
    }
    if (i < H3C * HC) g_wihb[i] = __float2bfloat16(wih[i]);
    if (i < HC * HC)  g_walb[i] = __float2bfloat16(Wal[i]);
    if (i < NRELC * HC) g_relb[i] = __float2bfloat16(rel[i]);
    if (i < HC * H3C) {
        int k = i / H3C, j = i % H3C;
        F[O_WHHT + i] = whh[j * 128 + k];
    }
    if (i < HC * HC) {
        int k = i / HC, j = i % HC;
        F[O_WH1T + i] = Wh1[j * HC + k];
        F[O_WH2T + i] = Wh2[j * HC + k];
        F[O_WATT + i] = Wat[j * HC + k];
        F[O_WALT + i] = Wal[j * HC + k];
    }
    if (i < 128 * 256) {
        int k = i / 256, j2 = i % 256;
        F[O_WM1T + i] = Wm1[j2 * 128 + k];
    }
    if (i < 256 * 128) {
        int k2 = i / 128, j = i % 128;
        F[O_WM2T + i] = Wm2[j * 256 + k2];
    }
    if (i < HC * (KPAD - NRELC)) {
        int j = i / (KPAD - NRELC), c = NRELC + i % (KPAD - NRELC);
        g_mrelTb[j * KPAD + c] = __float2bfloat16(0.f);
    }
    if (i < HC * (MT_STR - NRELC)) {
        int j = i / (MT_STR - NRELC), c = NRELC + i % (MT_STR - NRELC);
        F[O_MRELT + j * MT_STR + c] = 0.f;
    }
    if (i < NTC * NBC * (KPAD - NRELC)) {
        int row = i / (KPAD - NRELC), c = NRELC + i % (KPAD - NRELC);
        g_attnb[(size_t)row * KPAD + c] = __float2bfloat16(0.f);
    }
}

__global__ void k_count_entcvt(const int* __restrict__ dst, int* deg,
                               const float* __restrict__ ent) {
    int i = blockIdx.x * blockDim.x + threadIdx.x;
    if (i < NEC) atomicAdd(&deg[dst[i]], 1);
    if (i < N_ENTC * HC) g_entb[i] = __float2bfloat16(ent[i]);
}

__global__ void k_scanA(const int* __restrict__ deg, int* rowptr, int* bsums) {
    __shared__ int wsum[32];
    int tid = threadIdx.x, lane = tid & 31, wid = tid >> 5;
    int i = blockIdx.x * 1024 + tid;
    int v = (i < N_ENTC) ? deg[i] : 0;
    int x = v;
    #pragma unroll
    for (int o = 1; o < 32; o <<= 1) {
        int t = __shfl_up_sync(0xffffffffu, x, o);
        if (lane >= o) x += t;
    }
    if (lane == 31) wsum[wid] = x;
    __syncthreads();
    if (wid == 0) {
        int s = wsum[lane];
        #pragma unroll
        for (int o = 1; o < 32; o <<= 1) {
            int t = __shfl_up_sync(0xffffffffu, s, o);
            if (lane >= o) s += t;
        }
        wsum[lane] = s;
    }
    __syncthreads();
    int woff = (wid > 0) ? wsum[wid - 1] : 0;
    int incl = x + woff;
    if (i < N_ENTC) rowptr[i] = incl - v;
    if (tid == 1023) bsums[blockIdx.x] = incl;
}

__global__ void k_scanB(int* rowptr, const int* __restrict__ bsums, int nblk) {
    __shared__ int offs[32];
    __shared__ int total_s;
    int tid = threadIdx.x;
    if (tid < 32) {
        int v = (tid < nblk) ? bsums[tid] : 0;
        int x = v;
        #pragma unroll
        for (int o = 1; o < 32; o <<= 1) {
            int t = __shfl_up_sync(0xffffffffu, x, o);
            if (tid >= o) x += t;
        }
        offs[tid] = x - v;
        if (tid == 31) total_s = x;
    }
    __syncthreads();
    for (int i = tid; i < N_ENTC; i += blockDim.x)
        rowptr[i] += offs[i >> 10];
    if (tid == 0) rowptr[N_ENTC] = total_s;
}

__global__ void k_fill(const int* __restrict__ dst, const int* __restrict__ src,
                       const int* __restrict__ typ, const int* __restrict__ rowptr,
                       int* cursor, int* csr) {
    int e = blockIdx.x * blockDim.x + threadIdx.x;
    if (e < NEC) {
        int d = dst[e];
        int p = atomicAdd(&cursor[d], 1);
        csr[rowptr[d] + p] = src[e] | (typ[e] << 16);
    }
}

__global__ void k_aggregate(const int* __restrict__ rowptr, const int* __restrict__ csr) {
    int node = blockIdx.x;
    int c = threadIdx.x;  // 64
    __shared__ int s_src[256];
    __shared__ int s_typ[256];
    const __nv_bfloat162* entb = (const __nv_bfloat162*)g_entb;
    const __nv_bfloat162* relb = (const __nv_bfloat162*)g_relb;
    int beg = rowptr[node], end = rowptr[node + 1];
    int deg = end - beg;
    float ax = 0.f, ay = 0.f;
    for (int base = beg; base < end; base += 256) {
        int cnt = min(256, end - base);
        for (int i = c; i < cnt; i += 64) {
            int p = csr[base + i];
            s_src[i] = (p & 0xFFFF) << 6;
            s_typ[i] = ((unsigned)p >> 16) << 6;
        }
        __syncthreads();
        #pragma unroll 8
        for (int i = 0; i < cnt; i++) {
            __nv_bfloat162 ev = entb[s_src[i] + c];
            __nv_bfloat162 rv = relb[s_typ[i] + c];
            ax += __bfloat162float(ev.x) + __bfloat162float(rv.x);
            ay += __bfloat162float(ev.y) + __bfloat162float(rv.y);
        }
        __syncthreads();
    }
    float inv = (deg > 0) ? 1.f / (float)deg : 0.f;
    __nv_bfloat162 o;
    o.x = __float2bfloat16(ax * inv);
    o.y = __float2bfloat16(ay * inv);
    *(__nv_bfloat162*)(g_aggb + (size_t)node * HC + 2 * c) = o;
}

// ---------------- GEMM fragment helpers ----------------
#define BGM 128
#define BGN 128
#define BGK 32
#define SSTR 40
#define XSTR 136

#define MMA_STEP(As_, Bs_, STRA, kbaseA, kk, cacc)                                   \
    {                                                                                 \
        uint32_t a[2][4], b[8][2];                                                    \
        _Pragma("unroll")                                                             \
        for (int mt = 0; mt < 2; mt++) {                                              \
            int row = wm * 32 + mt * 16 + (lane & 15);                                \
            int col = (kbaseA) + (kk) + ((lane >> 4) << 3);                           \
            uint32_t addr = (uint32_t)__cvta_generic_to_shared((As_) + row * (STRA) + col); \
            asm volatile("ldmatrix.sync.aligned.m8n8.x4.shared.b16 {%0,%1,%2,%3},[%4];" \
                         : "=r"(a[mt][0]), "=r"(a[mt][1]), "=r"(a[mt][2]), "=r"(a[mt][3]) \
                         : "r"(addr));                                                \
        }                                                                             \
        _Pragma("unroll")                                                             \
        for (int np = 0; np < 4; np++) {                                              \
            int nrow = wn * 64 + np * 16 + ((lane >> 4) << 3) + (lane & 7);           \
            int ncol = (kk) + (((lane >> 3) & 1) << 3);                               \
            uint32_t addr = (uint32_t)__cvta_generic_to_shared((Bs_) + nrow * SSTR + ncol); \
            asm volatile("ldmatrix.sync.aligned.m8n8.x4.shared.b16 {%0,%1,%2,%3},[%4];" \
                         : "=r"(b[2 * np][0]), "=r"(b[2 * np][1]),                    \
                           "=r"(b[2 * np + 1][0]), "=r"(b[2 * np + 1][1])             \
                         : "r"(addr));                                                \
        }                                                                             \
        _Pragma("unroll")                                                             \
        for (int mt = 0; mt < 2; mt++)                                                \
            _Pragma("unroll")                                                         \
            for (int nt = 0; nt < 8; nt++)                                            \
                asm volatile(                                                         \
                    "mma.sync.aligned.m16n8k16.row.col.f32.bf16.bf16.f32 "            \
                    "{%0,%1,%2,%3},{%4,%5,%6,%7},{%8,%9},{%0,%1,%2,%3};"              \
                    : "+f"(cacc[mt][nt][0]), "+f"(cacc[mt][nt][1]),                   \
                      "+f"(cacc[mt][nt][2]), "+f"(cacc[mt][nt][3])                    \
                    : "r"(a[mt][0]), "r"(a[mt][1]), "r"(a[mt][2]), "r"(a[mt][3]),     \
                      "r"(b[nt][0]), "r"(b[nt][1]));                                  \
    }

// ---------------- score GEMM + fused final (cp.async 2-stage pipeline) ----------------
__global__ __launch_bounds__(256, 2)
void k_score(const __nv_bfloat16* __restrict__ A, const __nv_bfloat16* __restrict__ B,
             float* __restrict__ Cf, const int* __restrict__ trip, double* acc,
             int* done, int nblocks, int write_final, int M, int N) {
    extern __shared__ __nv_bfloat16 smd[];
    __nv_bfloat16* As0 = smd;
    __nv_bfloat16* As1 = smd + BGM * SSTR;
    __nv_bfloat16* Bs0 = smd + 2 * BGM * SSTR;
    __nv_bfloat16* Bs1 = smd + 3 * BGM * SSTR;
    int tid = threadIdx.x;
    int lane = tid & 31, wid = tid >> 5;
    int wm = wid & 3, wn = wid >> 2;
    int rowBase = blockIdx.y * BGM;
    int colBase = blockIdx.x * BGN;
    float c[2][8][4];
    #pragma unroll
    for (int i = 0; i < 2; i++)
        #pragma unroll
        for (int j = 0; j < 8; j++)
            #pragma unroll
            for (int q = 0; q < 4; q++) c[i][j][q] = 0.f;
    auto pf = [&](int k0, int bi) {
        __nv_bfloat16* Ad = bi ? As1 : As0;
        __nv_bfloat16* Bd = bi ? Bs1 : Bs0;
        #pragma unroll
        for (int i = 0; i < 2; i++) {
            int idx = tid + i * 256;
            int r = idx >> 2, seg = idx & 3;
            cpa16(Ad + r * SSTR + seg * 8,
                  A + (size_t)(rowBase + r) * HC + k0 + seg * 8);
            int gn = colBase + r;
            bool ok = gn < N;
            cpa16z(Bd + r * SSTR + seg * 8,
                   B + (size_t)(ok ? gn : 0) * HC + k0 + seg * 8, ok);
        }
        CP_COMMIT();
    };
    const int T = HC / BGK;  // 4
    pf(0, 0);
    pf(BGK, 1);
    for (int t = 0; t < T; t++) {
        if (t + 1 < T) CP_WAIT1(); else CP_WAIT0();
        __syncthreads();
        __nv_bfloat16* Ac = (t & 1) ? As1 : As0;
        __nv_bfloat16* Bc = (t & 1) ? Bs1 : Bs0;
        MMA_STEP(Ac, Bc, SSTR, 0, 0, c)
        MMA_STEP(Ac, Bc, SSTR, 0, 16, c)
        __syncthreads();
        if (t + 2 < T) pf((t + 2) * BGK, t & 1);
    }
    float lsp = 0.f, lxo = 0.f;
    #pragma unroll
    for (int mt = 0; mt < 2; mt++) {
        int r0 = rowBase + wm * 32 + mt * 16 + (lane >> 2);
        int ob0 = trip[r0 * 3 + 2];
        int ob1 = trip[(r0 + 8) * 3 + 2];
        #pragma unroll
        for (int nt = 0; nt < 8; nt++) {
            int col = colBase + wn * 64 + nt * 8 + ((lane & 3) << 1);
            if (col < N) {
                #pragma unroll
                for (int half = 0; half < 2; half++) {
                    int row = r0 + half * 8;
                    int ob = half ? ob1 : ob0;
                    float x0 = c[mt][nt][half * 2 + 0];
                    float x1 = c[mt][nt][half * 2 + 1];
                    float s0, p0, s1, p1;
                    sig_sp(x0, s0, p0);
                    sig_sp(x1, s1, p1);
                    *(float2*)(Cf + (size_t)row * N + col) = make_float2(s0, s1);
                    lsp += p0 + p1;
                    if (col == ob) lxo += x0;
                    if (col + 1 == ob) lxo += x1;
                }
            }
        }
    }
    float bs = blockReduceSum(lsp);
    float bx = blockReduceSum(lxo);
    if (tid == 0) {
        atomicAdd(&acc[0], (double)bs);
        atomicAdd(&acc[1], (double)bx);
        __threadfence();
        int old = atomicAdd(done, 1);
        if (old == nblocks - 1 && write_final) {
            double a0 = atomicAdd(&acc[0], 0.0);
            double a1 = atomicAdd(&acc[1], 0.0);
            double a2 = atomicAdd(&acc[2], 0.0);
            Cf[(size_t)NBC * N_ENTC]     = (float)(a2 / (double)(NBC * HC));
            Cf[(size_t)NBC * N_ENTC + 1] = (float)((a0 - a1) /
                                                   ((double)NBC * (double)N_ENTC));
        }
    }
}

// ---------------- fused pre+aln (cp.async 2-stage pipeline) ----------------
__global__ __launch_bounds__(256, 2)
void k_prealn(const float* __restrict__ bal, const int* __restrict__ deg, int M) {
    extern __shared__ __nv_bfloat16 smd[];
    __nv_bfloat16* As0 = smd;
    __nv_bfloat16* As1 = smd + BGM * SSTR;
    __nv_bfloat16* Bs0 = smd + 2 * BGM * SSTR;
    __nv_bfloat16* Bs1 = smd + 3 * BGM * SSTR;
    __nv_bfloat16* Xs  = smd + 4 * BGM * SSTR;
    int tid = threadIdx.x, lane = tid & 31, wid = tid >> 5;
    int wm = wid & 3, wn = wid >> 2;
    int rowBase = blockIdx.x * BGM;
    int lr[2]; bool lv[2], lm[2];
    #pragma unroll
    for (int i = 0; i < 2; i++) {
        int idx = tid + i * 256;
        lr[i] = idx >> 2;
        int gr = rowBase + lr[i];
        lv[i] = gr < M;
        lm[i] = lv[i] && (deg[lv[i] ? gr : 0] > 0);
    }
    float c[2][8][4];
    #pragma unroll
    for (int i = 0; i < 2; i++)
        #pragma unroll
        for (int j = 0; j < 8; j++)
            #pragma unroll
            for (int q = 0; q < 4; q++) c[i][j][q] = 0.f;
    auto pfa = [&](int k0, int bi) {
        __nv_bfloat16* Ad = bi ? As1 : As0;
        __nv_bfloat16* Bd = bi ? Bs1 : Bs0;
        #pragma unroll
        for (int i = 0; i < 2; i++) {
            int idx = tid + i * 256;
            int r = lr[i], seg = idx & 3;
            int gr = rowBase + r;
            int kc = k0 + seg * 8;
            const __nv_bfloat16* src;
            bool ok;
            if (k0 < 128)      { src = g_aggb + (size_t)gr * HC + kc;       ok = lv[i]; }
            else if (k0 < 256) { src = g_entb + (size_t)gr * HC + kc - 128; ok = lm[i]; }
            else               { src = g_entb + (size_t)gr * HC + kc - 256; ok = lv[i] && !lm[i]; }
            cpa16z(Ad + r * SSTR + seg * 8, ok ? src : (const __nv_bfloat16*)g_aggb, ok);
            cpa16(Bd + r * SSTR + seg * 8, g_B3 + (size_t)r * KPRE + k0 + seg * 8);
        }
        CP_COMMIT();
    };
    const int T1 = KPRE / BGK;  // 12
    pfa(0, 0);
    pfa(BGK, 1);
    for (int t = 0; t < T1; t++) {
        if (t + 1 < T1) CP_WAIT1(); else CP_WAIT0();
        __syncthreads();
        __nv_bfloat16* Ac = (t & 1) ? As1 : As0;
        __nv_bfloat16* Bc = (t & 1) ? Bs1 : Bs0;
        MMA_STEP(Ac, Bc, SSTR, 0, 0, c)
        MMA_STEP(Ac, Bc, SSTR, 0, 16, c)
        __syncthreads();
        if (t + 2 < T1) pfa((t + 2) * BGK, t & 1);
    }
    // stage-1 epilogue: rrelu -> Xs + prebf
    #pragma unroll
    for (int mt = 0; mt < 2; mt++) {
        #pragma unroll
        for (int nt = 0; nt < 8; nt++) {
            int colL = wn * 64 + nt * 8 + ((lane & 3) << 1);
            #pragma unroll
            for (int half = 0; half < 2; half++) {
                int rowL = wm * 32 + mt * 16 + (lane >> 2) + half * 8;
                float v0 = c[mt][nt][half * 2 + 0];
                float v1 = c[mt][nt][half * 2 + 1];
                v0 = (v0 >= 0.f) ? v0 : v0 * SLOPE;
                v1 = (v1 >= 0.f) ? v1 : v1 * SLOPE;
                __nv_bfloat162 bv(__float2bfloat16(v0), __float2bfloat16(v1));
                *(__nv_bfloat162*)(Xs + rowL * XSTR + colL) = bv;
                int grow = rowBase + rowL;
                if (grow < M)
                    *(__nv_bfloat162*)(g_prebf + (size_t)grow * HC + colL) = bv;
            }
        }
    }
    __syncthreads();
    // stage 2: aln = Xs @ Wal^T + bal (B-only cp.async pipeline)
    float c2[2][8][4];
    #pragma unroll
    for (int i = 0; i < 2; i++)
        #pragma unroll
        for (int j = 0; j < 8; j++)
            #pragma unroll
            for (int q = 0; q < 4; q++) c2[i][j][q] = 0.f;
    auto pfb = [&](int k0, int bi) {
        __nv_bfloat16* Bd = bi ? Bs1 : Bs0;
        #pragma unroll
        for (int i = 0; i < 2; i++) {
            int idx = tid + i * 256;
            int r = idx >> 2, seg = idx & 3;
            cpa16(Bd + r * SSTR + seg * 8, g_walb + (size_t)r * HC + k0 + seg * 8);
        }
        CP_COMMIT();
    };
    const int T2 = HC / BGK;  // 4
    pfb(0, 0);
    pfb(BGK, 1);
    for (int t = 0; t < T2; t++) {
        if (t + 1 < T2) CP_WAIT1(); else CP_WAIT0();
        __syncthreads();
        __nv_bfloat16* Bc = (t & 1) ? Bs1 : Bs0;
        MMA_STEP(Xs, Bc, XSTR, t * BGK, 0, c2)
        MMA_STEP(Xs, Bc, XSTR, t * BGK, 16, c2)
        __syncthreads();
        if (t + 2 < T2) pfb((t + 2) * BGK, t & 1);
    }
    #pragma unroll
    for (int mt = 0; mt < 2; mt++) {
        #pragma unroll
        for (int nt = 0; nt < 8; nt++) {
            int colL = wn * 64 + nt * 8 + ((lane & 3) << 1);
            float b0 = bal[colL], b1 = bal[colL + 1];
            #pragma unroll
            for (int half = 0; half < 2; half++) {
                int grow = rowBase + wm * 32 + mt * 16 + (lane >> 2) + half * 8;
                if (grow < M) {
                    __nv_bfloat162 bv(__float2bfloat16(c2[mt][nt][half * 2 + 0] + b0),
                                      __float2bfloat16(c2[mt][nt][half * 2 + 1] + b1));
                    *(__nv_bfloat162*)(g_alnbf + (size_t)grow * HC + colL) = bv;
                }
            }
        }
    }
}

// ---------------- fused softmax+rpath+giall (R13 register-prefetch version) ----------------
__global__ __launch_bounds__(256)
void k_rpgi(const float* __restrict__ part, const float* __restrict__ Amat,
            const float* __restrict__ bih, float* __restrict__ giall) {
    extern __shared__ __nv_bfloat16 sm[];
    __nv_bfloat16* As = sm;
    __nv_bfloat16* Bs = sm + BGM * SSTR;
    __nv_bfloat16* Xs = sm + 2 * BGM * SSTR;
    int tid = threadIdx.x, lane = tid & 31, wid = tid >> 5;
    int wm = wid & 3, wn = wid >> 2;
    int rowBase = blockIdx.x * BGM;
    uint4 pa[2], pb[2];
    if (blockIdx.x < 64) {
        for (int rr = wid; rr < BGM; rr += 8) {
            int grow = rowBase + rr;
            int t = grow >> 10, b = grow & 1023;
            const float* prow = part + (size_t)b * (NTC * NRELC) + t * NRELC;
            const float* arow = Amat + (size_t)b * NRELC;
            float xv[15];
            float m = -3.402823e38f;
            #pragma unroll
            for (int i = 0; i < 15; i++) {
                int cc = lane + i * 32;
                float x = -3.402823e38f;
                if (cc < NRELC) {
                    float val = prow[cc] * arow[cc];
                    x = (val == 0.f) ? -1e9f : val;
                }
                xv[i] = x;
                m = fmaxf(m, x);
            }
            #pragma unroll
            for (int o = 16; o > 0; o >>= 1) m = fmaxf(m, __shfl_xor_sync(0xffffffffu, m, o));
            float s = 0.f;
            float ev[15];
            #pragma unroll
            for (int i = 0; i < 15; i++) {
                int cc = lane + i * 32;
                float e = (cc < NRELC) ? __expf(xv[i] - m) : 0.f;
                ev[i] = e;
                s += e;
            }
            #pragma unroll
            for (int o = 16; o > 0; o >>= 1) s += __shfl_xor_sync(0xffffffffu, s, o);
            float inv = 1.f / s;
            __nv_bfloat16* orow = g_attnb + (size_t)grow * KPAD;
            #pragma unroll
            for (int i = 0; i < 15; i++) {
                int cc = lane + i * 32;
                if (cc < NRELC) orow[cc] = __float2bfloat16(ev[i] * inv);
            }
        }
        __syncthreads();
        float c[2][8][4];
        #pragma unroll
        for (int i = 0; i < 2; i++)
            #pragma unroll
            for (int j = 0; j < 8; j++)
                #pragma unroll
                for (int q = 0; q < 4; q++) c[i][j][q] = 0.f;
        #pragma unroll
        for (int i = 0; i < 2; i++) {
            int idx = tid + i * 256;
            int r = idx >> 2, seg = idx & 3;
            pa[i] = *(const uint4*)(g_attnb + (size_t)(rowBase + r) * KPAD + seg * 8);
            pb[i] = *(const uint4*)(g_mrelTb + (size_t)r * KPAD + seg * 8);
        }
        for (int k0 = 0; k0 < KPAD; k0 += BGK) {
            #pragma unroll
            for (int i = 0; i < 2; i++) {
                int idx = tid + i * 256;
                int r = idx >> 2, seg = idx & 3;
                *(uint4*)(As + r * SSTR + seg * 8) = pa[i];
                *(uint4*)(Bs + r * SSTR + seg * 8) = pb[i];
            }
            __syncthreads();
            if (k0 + BGK < KPAD) {
                #pragma unroll
                for (int i = 0; i < 2; i++) {
                    int idx = tid + i * 256;
                    int r = idx >> 2, seg = idx & 3;
                    pa[i] = *(const uint4*)(g_attnb + (size_t)(rowBase + r) * KPAD + k0 + BGK + seg * 8);
                    pb[i] = *(const uint4*)(g_mrelTb + (size_t)r * KPAD + k0 + BGK + seg * 8);
                }
            }
            MMA_STEP(As, Bs, SSTR, 0, 0, c)
            MMA_STEP(As, Bs, SSTR, 0, 16, c)
            __syncthreads();
        }
        #pragma unroll
        for (int mt = 0; mt < 2; mt++)
            #pragma unroll
            for (int nt = 0; nt < 8; nt++) {
                int colL = wn * 64 + nt * 8 + ((lane & 3) << 1);
                #pragma unroll
                for (int half = 0; half < 2; half++) {
                    int rowL = wm * 32 + mt * 16 + (lane >> 2) + half * 8;
                    __nv_bfloat162 bv(__float2bfloat16(c[mt][nt][half * 2 + 0]),
                                      __float2bfloat16(c[mt][nt][half * 2 + 1]));
                    *(__nv_bfloat162*)(Xs + rowL * XSTR + colL) = bv;
                }
            }
    } else {
        for (int i = tid; i < BGM * (HC / 8); i += 256) {
            int r = i / (HC / 8), seg = i % (HC / 8);
            *(uint4*)(Xs + r * XSTR + seg * 8) =
                *(const uint4*)(g_Xb + (size_t)(rowBase + r) * HC + seg * 8);
        }
    }
    __syncthreads();
    for (int nb = 0; nb < 3; nb++) {
        float c2[2][8][4];
        #pragma unroll
        for (int i = 0; i < 2; i++)
            #pragma unroll
            for (int j = 0; j < 8; j++)
                #pragma unroll
                for (int q = 0; q < 4; q++) c2[i][j][q] = 0.f;
        #pragma unroll
        for (int i = 0; i < 2; i++) {
            int idx = tid + i * 256;
            int r = idx >> 2, seg = idx & 3;
            pb[i] = *(const uint4*)(g_wihb + (size_t)(nb * 128 + r) * HC + seg * 8);
        }
        for (int k0 = 0; k0 < HC; k0 += BGK) {
            #pragma unroll
            for (int i = 0; i < 2; i++) {
                int idx = tid + i * 256;
                int r = idx >> 2, seg = idx & 3;
                *(uint4*)(Bs + r * SSTR + seg * 8) = pb[i];
            }
            __syncthreads();
            if (k0 + BGK < HC) {
                #pragma unroll
                for (int i = 0; i < 2; i++) {
                    int idx = tid + i * 256;
                    int r = idx >> 2, seg = idx & 3;
                    pb[i] = *(const uint4*)(g_wihb + (size_t)(nb * 128 + r) * HC + k0 + BGK + seg * 8);
                }
            }
            MMA_STEP(Xs, Bs, XSTR, k0, 0, c2)
            MMA_STEP(Xs, Bs, XSTR, k0, 16, c2)
            __syncthreads();
        }
        #pragma unroll
        for (int mt = 0; mt < 2; mt++)
            #pragma unroll
            for (int nt = 0; nt < 8; nt++) {
                int colL = wn * 64 + nt * 8 + ((lane & 3) << 1);
                int col = nb * 128 + colL;
                float b0 = bih[col], b1 = bih[col + 1];
                #pragma unroll
                for (int half = 0; half < 2; half++) {
                    int row = rowBase + wm * 32 + mt * 16 + (lane >> 2) + half * 8;
                    *(float2*)(giall + (size_t)row * H3C + col) =
                        make_float2(c2[mt][nt][half * 2 + 0] + b0,
                                    c2[mt][nt][half * 2 + 1] + b1);
                }
            }
    }
}

// ---------------- fused mapped_rel ----------------
__global__ __launch_bounds__(256)
void k_mrel(const float* __restrict__ rel, const float* __restrict__ Wm1T,
            const float* __restrict__ Wm2T, const float* __restrict__ bm1,
            const float* __restrict__ bm2, float* __restrict__ mrel,
            float* __restrict__ mrelT) {
    __shared__ float rels[10][128];
    __shared__ float p1s[10][256];
    int tid = threadIdx.x;
    int r0 = blockIdx.x * 10;
    for (int i = tid; i < 10 * 128; i += 256)
        rels[i >> 7][i & 127] = rel[(r0 + (i >> 7)) * 128 + (i & 127)];
    __syncthreads();
    {
        int j2 = tid;
        float a[10];
        #pragma unroll
        for (int r = 0; r < 10; r++) a[r] = 0.f;
        for (int k = 0; k < 128; k++) {
            float w = Wm1T[k * 256 + j2];
            #pragma unroll
            for (int r = 0; r < 10; r++) a[r] = fmaf(rels[r][k], w, a[r]);
        }
        float b = bm1[j2];
        #pragma unroll
        for (int r = 0; r < 10; r++) p1s[r][j2] = a[r] + b;
    }
    __syncthreads();
    {
        int j = tid & 127, half = tid >> 7;
        float a[5];
        #pragma unroll
        for (int r = 0; r < 5; r++) a[r] = 0.f;
        for (int k = 0; k < 256; k++) {
            float w = Wm2T[k * 128 + j];
            #pragma unroll
            for (int r = 0; r < 5; r++) a[r] = fmaf(p1s[half * 5 + r][k], w, a[r]);
        }
        float b = bm2[j];
        #pragma unroll
        for (int r = 0; r < 5; r++) {
            int row = r0 + half * 5 + r;
            float v = a[r] + b;
            mrel[row * 128 + j] = v;
            mrelT[j * MT_STR + row] = v;
            g_mrelTb[j * KPAD + row] = __float2bfloat16(v);
        }
    }
}

__global__ __launch_bounds__(128)
void k_qa_amat(const float* __restrict__ mrel, const int* __restrict__ trip,
               const float* __restrict__ WatT, const float* __restrict__ bat,
               const float* __restrict__ mrelT, float* __restrict__ qrel,
               float* __restrict__ Amat) {
    __shared__ float q[4][128];
    __shared__ float qa[4][128];
    int j = threadIdx.x;
    int r0 = blockIdx.x * 4;
    #pragma unroll
    for (int r = 0; r < 4; r++) {
        float v = mrel[(size_t)trip[(r0 + r) * 3 + 1] * HC + j];
        q[r][j] = v;
        qrel[(r0 + r) * 128 + j] = v;
        g_Xb[(size_t)(NTC * NBC + r0 + r) * HC + j] = __float2bfloat16(v);
    }
    __syncthreads();
    {
        float a[4] = {0.f, 0.f, 0.f, 0.f};
        for (int k = 0; k < 128; k++) {
            float w = WatT[k * 128 + j];
            #pragma unroll
            for (int r = 0; r < 4; r++) a[r] = fmaf(q[r][k], w, a[r]);
        }
        float b = bat[j];
        #pragma unroll
        for (int r = 0; r < 4; r++) qa[r][j] = a[r] + b;
    }
    __syncthreads();
    float a[4][4];
    #pragma unroll
    for (int r = 0; r < 4; r++)
        #pragma unroll
        for (int t = 0; t < 4; t++) a[r][t] = 0.f;
    for (int k = 0; k < 128; k++) {
        float m0 = mrelT[k * MT_STR + j];
        float m1 = mrelT[k * MT_STR + j + 128];
        float m2 = mrelT[k * MT_STR + j + 256];
        float m3 = mrelT[k * MT_STR + j + 384];
        #pragma unroll
        for (int r = 0; r < 4; r++) {
            float qv = qa[r][k];
            a[r][0] = fmaf(qv, m0, a[r][0]);
            a[r][1] = fmaf(qv, m1, a[r][1]);
            a[r][2] = fmaf(qv, m2, a[r][2]);
            a[r][3] = fmaf(qv, m3, a[r][3]);
        }
    }
    #pragma unroll
    for (int r = 0; r < 4; r++)
        #pragma unroll
        for (int t = 0; t < 4; t++) {
            int n = j + t * 128;
            if (n < NRELC) Amat[(size_t)(r0 + r) * NRELC + n] = a[r][t];
        }
}

// ---------------- mega GRU kernel ----------------
__global__ __launch_bounds__(384)
void k_gru_all(const float* __restrict__ giall, const float* __restrict__ whhT,
               const float* __restrict__ bhh, const float* __restrict__ qrel,
               const float* __restrict__ Wh1T, const float* __restrict__ Wh2T,
               const float* __restrict__ bh1, const float* __restrict__ bh2,
               const int* __restrict__ trip, const float* __restrict__ WalT,
               const float* __restrict__ bal, double* acc) {
    extern __shared__ float swhh[];
    __shared__ float hs[8][128];
    __shared__ float asg[8][384];
    __shared__ float qs[8][128];
    __shared__ float ps[8][128];
    int tid = threadIdx.x;
    int j = tid & 127;
    int g = tid >> 7;
    int r0 = blockIdx.x * 8;

    for (int i = tid; i < HC * H3C; i += 384) swhh[i] = whhT[i];
    for (int i = tid; i < 8 * 128; i += 384) hs[i >> 7][i & 127] = 0.f;
    __syncthreads();

    for (int t = 0; t < NTC; t++) {
        {
            float a[8];
            #pragma unroll
            for (int r = 0; r < 8; r++) a[r] = 0.f;
            for (int k = 0; k < 128; k++) {
                float w = swhh[k * H3C + tid];
                #pragma unroll
                for (int r = 0; r < 8; r++) a[r] = fmaf(hs[r][k], w, a[r]);
            }
            #pragma unroll
            for (int r = 0; r < 8; r++) asg[r][tid] = a[r];
        }
        __syncthreads();
        if (tid < 128) {
            float br = bhh[j], bz = bhh[128 + j], bn = bhh[256 + j];
            const float* gi = giall + (size_t)t * NBC * H3C;
            #pragma unroll
            for (int r = 0; r < 8; r++) {
                size_t gx = (size_t)(r0 + r) * H3C;
                float rr = sigm(gi[gx + j] + asg[r][j] + br);
                float zz = sigm(gi[gx + 128 + j] + asg[r][128 + j] + bz);
                float nn = tanhf(gi[gx + 256 + j] + rr * (asg[r][256 + j] + bn));
                hs[r][j] = (1.f - zz) * nn + zz * hs[r][j];
            }
        }
        __syncthreads();
    }

    for (int i = tid; i < 8 * 128; i += 384)
        qs[i >> 7][i & 127] = qrel[(r0 + (i >> 7)) * 128 + (i & 127)];
    __syncthreads();

    for (int r = g; r < 8; r += 3) {
        float a = 0.f;
        for (int k = 0; k < 128; k++) a = fmaf(qs[r][k], Wh1T[k * 128 + j], a);
        ps[r][j] = a + bh1[j];
    }
    __syncthreads();
    float predv[3];
    int nmine = 0;
    for (int r = g; r < 8; r += 3) {
        float a = 0.f;
        for (int k = 0; k < 128; k++) a = fmaf(ps[r][k], Wh2T[k * 128 + j], a);
        predv[nmine++] = 0.1f * (a + bh2[j]) + qs[r][j];
    }
    __syncthreads();
    {
        int m = 0;
        for (int r = g; r < 8; r += 3) ps[r][j] = predv[m++];
    }
    __syncthreads();
    {
        float msum = 0.f;
        for (int r = g; r < 8; r += 3) {
            float d = ps[r][j] - hs[r][j];
            msum += d * d;
        }
        float bsum = blockReduceSum(msum);
        if (tid == 0) atomicAdd(&acc[2], (double)bsum);
    }
    __syncthreads();
    {
        float a[8];
        #pragma unroll
        for (int r = 0; r < 8; r++) a[r] = 0.f;
        for (int k = 0; k < 128; k++) {
            float w = swhh[k * H3C + tid];
            #pragma unroll
            for (int r = 0; r < 8; r++) a[r] = fmaf(ps[r][k], w, a[r]);
        }
        #pragma unroll
        for (int r = 0; r < 8; r++) asg[r][tid] = a[r];
    }
    __syncthreads();
    if (tid < 128) {
        float br = bhh[j], bz = bhh[128 + j], bn = bhh[256 + j];
        const float* gi = giall + (size_t)NTC * NBC * H3C;
        #pragma unroll
        for (int r = 0; r < 8; r++) {
            size_t gx = (size_t)(r0 + r) * H3C;
            float rr = sigm(gi[gx + j] + asg[r][j] + br);
            float zz = sigm(gi[gx + 128 + j] + asg[r][128 + j] + bz);
            float nn = tanhf(gi[gx + 256 + j] + rr * (asg[r][256 + j] + bn));
            hs[r][j] = (1.f - zz) * nn + zz * ps[r][j];
        }
    }
    __syncthreads();
    for (int i = tid; i < 8 * 128; i += 384) {
        int r = i >> 7, c = i & 127;
        int row = trip[(r0 + r) * 3 + 0];
        qs[r][c] = __bfloat162float(g_prebf[(size_t)row * HC + c]);
    }
    __syncthreads();
    for (int r = g; r < 8; r += 3) {
        float a = 0.f;
        for (int k = 0; k < 128; k++) a = fmaf(qs[r][k], WalT[k * 128 + j], a);
        float v = (a + bal[j]) * hs[r][j];
        g_svecb[(r0 + r) * 128 + j] = __float2bfloat16(v);
    }
}

// ---------------- host ----------------
extern "C" void kernel_launch(void* const* d_in, const int* in_sizes, int n_in,
                              void* d_out, int out_size) {
    const float* ent  = (const float*)d_in[0];
    const float* rel  = (const float*)d_in[1];
    const float* Wn   = (const float*)d_in[2];
    const float* Wl   = (const float*)d_in[3];
    const float* Wev  = (const float*)d_in[4];
    const float* wih  = (const float*)d_in[5];
    const float* whh  = (const float*)d_in[6];
    const float* bih  = (const float*)d_in[7];
    const float* bhh  = (const float*)d_in[8];
    const float* Wm1  = (const float*)d_in[9];
    const float* bm1  = (const float*)d_in[10];
    const float* Wm2  = (const float*)d_in[11];
    const float* bm2  = (const float*)d_in[12];
    const float* Wh1  = (const float*)d_in[13];
    const float* bh1  = (const float*)d_in[14];
    const float* Wh2  = (const float*)d_in[15];
    const float* bh2  = (const float*)d_in[16];
    const float* Wal  = (const float*)d_in[17];
    const float* bal  = (const float*)d_in[18];
    const float* Wat  = (const float*)d_in[19];
    const float* bat  = (const float*)d_in[20];
    const float* part = (const float*)d_in[21];
    const int* esrc = (const int*)d_in[22];
    const int* edst = (const int*)d_in[23];
    const int* etyp = (const int*)d_in[24];
    const int* trip = (const int*)d_in[25];
    float* out = (float*)d_out;

    void* basep = nullptr;
    cudaGetSymbolAddress(&basep, d_buf);
    float* F = (float*)basep;
    __nv_bfloat16 *pSvecb, *pAlnb;
    { void* p; cudaGetSymbolAddress(&p, g_svecb); pSvecb = (__nv_bfloat16*)p; }
    { void* p; cudaGetSymbolAddress(&p, g_alnbf); pAlnb  = (__nv_bfloat16*)p; }

    float* mrel   = F + O_MREL;
    float* mrelT  = F + O_MRELT;
    float* qrel   = F + O_QREL;
    float* Amat   = F + O_AMAT;
    float* giall  = F + O_GIALL;
    float* whhT   = F + O_WHHT;
    float* Wh1T   = F + O_WH1T;
    float* Wh2T   = F + O_WH2T;
    float* WatT   = F + O_WATT;
    float* WalT   = F + O_WALT;
    float* Wm1T   = F + O_WM1T;
    float* Wm2T   = F + O_WM2T;
    double* acc   = (double*)(F + O_ACC);
    int* deg      = (int*)(F + O_INT);
    int* rowptr   = deg + N_ENTC;
    int* cursor   = rowptr + N_ENTC + 1;
    int* csr      = cursor + N_ENTC;
    int* bsums    = csr + NEC;
    int* done     = bsums + 32;

    const int RPGI_SMEM   = (2 * BGM * SSTR + BGM * XSTR) * 2;       // 55296 B
    const int SCORE_SMEM  = 4 * BGM * SSTR * 2;                      // 40960 B
    const int PREALN_SMEM = 4 * BGM * SSTR * 2 + BGM * XSTR * 2;     // 75776 B
    const int GRU_SMEM = HC * H3C * 4;                               // 196608 B
    static bool s_init = false;
    static cudaStream_t sB = 0;
    static cudaEvent_t evF = 0, evB = 0;
    if (!s_init) {
        cudaFuncSetAttribute(k_prealn, cudaFuncAttributeMaxDynamicSharedMemorySize, PREALN_SMEM);
        cudaFuncSetAttribute(k_rpgi,   cudaFuncAttributeMaxDynamicSharedMemorySize, RPGI_SMEM);
        cudaFuncSetAttribute(k_score,  cudaFuncAttributeMaxDynamicSharedMemorySize, SCORE_SMEM);
        cudaFuncSetAttribute(k_gru_all, cudaFuncAttributeMaxDynamicSharedMemorySize, GRU_SMEM);
        cudaStreamCreateWithFlags(&sB, cudaStreamNonBlocking);
        cudaEventCreateWithFlags(&evF, cudaEventDisableTiming);
        cudaEventCreateWithFlags(&evB, cudaEventDisableTiming);
        s_init = true;
    }

    k_init<<<640, 256>>>(Wn, Wl, Wev, wih, whh, Wal, Wh1, Wh2, Wat, Wm1, Wm2, rel,
                         deg, cursor, acc, done, F);
    cudaEventRecord(evF, 0);
    cudaStreamWaitEvent(sB, evF, 0);

    // ---- chain B (relation path) on sB ----
    k_mrel<<<46, 256, 0, sB>>>(rel, Wm1T, Wm2T, bm1, bm2, mrel, mrelT);
    k_qa_amat<<<256, 128, 0, sB>>>(mrel, trip, WatT, bat, mrelT, qrel, Amat);
    k_rpgi<<<(NTC + 1) * NBC / BGM, 256, RPGI_SMEM, sB>>>(part, Amat, bih, giall);
    cudaEventRecord(evB, sB);

    // ---- chain A (entity path) on default stream ----
    k_count_entcvt<<<(N_ENTC * HC + 255) / 256, 256>>>(edst, deg, ent);
    k_scanA<<<(N_ENTC + 1023) / 1024, 1024>>>(deg, rowptr, bsums);
    k_scanB<<<1, 1024>>>(rowptr, bsums, (N_ENTC + 1023) / 1024);
    k_fill<<<(NEC + 255) / 256, 256>>>(edst, esrc, etyp, rowptr, cursor, csr);
    k_aggregate<<<N_ENTC, 64>>>(rowptr, csr);
    k_prealn<<<(N_ENTC + BGM - 1) / BGM, 256, PREALN_SMEM>>>(bal, deg, N_ENTC);

    // ---- join ----
    cudaStreamWaitEvent(0, evB, 0);
    k_gru_all<<<128, 384, GRU_SMEM>>>(giall, whhT, bhh, qrel, Wh1T, Wh2T, bh1, bh2,
                                      trip, WalT, bal, acc);
    {
        dim3 g((N_ENTC + BGN - 1) / BGN, NBC / BGM);
        int nblocks = g.x * g.y;
        int wf = (out_size >= NBC * N_ENTC + 2) ? 1 : 0;
        k_score<<<g, 256, SCORE_SMEM>>>(pSvecb, pAlnb, out, trip, acc, done, nblocks, wf,
                                        NBC, N_ENTC);
    }
}